// round 2
// baseline (speedup 1.0000x reference)
#include <cuda_runtime.h>

// Problem constants (fixed shapes from reference)
#define BB 4
#define HH 16
#define SS_ 2048
#define DD 128
#define BM 128     // query rows per block
#define BN 64      // keys per inner tile
#define NTH 256

// scratch: inverse row sums, [B*H*S]
__device__ float g_inv_rowsum[BB * HH * SS_];

// smem layout (floats):
//  Qs  [BM][132]   padded row-major
//  Ks  [BN][132]
//  Vs  [BN][128]
//  Es  [BN][132]   e transposed: [key][row]
//  Red [BM][16]
#define QS_STRIDE 132
#define KS_STRIDE 132
#define VS_STRIDE 128
#define ES_STRIDE 132

__global__ __launch_bounds__(NTH, 1)
void attn_main(const float* __restrict__ q,
               const float* __restrict__ k,
               const float* __restrict__ v,
               const int*   __restrict__ mask,
               float* __restrict__ out,
               float* __restrict__ attn,
               int write_attn)
{
    extern __shared__ float sm[];
    float* Qs  = sm;
    float* Ks  = Qs + BM * QS_STRIDE;
    float* Vs  = Ks + BN * KS_STRIDE;
    float* Es  = Vs + BN * VS_STRIDE;
    float* Red = Es + BN * ES_STRIDE;

    const int tid = threadIdx.x;
    const int ty  = tid >> 4;    // 0..15  (row group: 8 rows each)
    const int tx  = tid & 15;    // 0..15

    const int qblock = blockIdx.x;       // 0..S/BM-1
    const int bh     = blockIdx.y;       // 0..B*H-1
    const int b      = bh / HH;
    const int q0     = qblock * BM;

    const size_t head_base = (size_t)bh * SS_ * DD;
    const float* qptr = q + head_base + (size_t)q0 * DD;

    // ---- load Q tile [BM][D] into padded smem ----
    #pragma unroll
    for (int t = tid; t < BM * (DD / 4); t += NTH) {
        int row = t >> 5;          // /32
        int c4  = t & 31;
        float4 val = ((const float4*)(qptr + (size_t)row * DD))[c4];
        *(float4*)(Qs + row * QS_STRIDE + c4 * 4) = val;
    }

    // PV accumulators: rows ty*8+i, D-columns tx*8+j (covers all 128 cols)
    float out_acc[8][8];
    float rsum[8];
    #pragma unroll
    for (int i = 0; i < 8; i++) {
        rsum[i] = 0.f;
        #pragma unroll
        for (int j = 0; j < 8; j++) out_acc[i][j] = 0.f;
    }

    const float scale = 0.08838834764831843f;   // 1/sqrt(128)
    const int* mbase = mask + ((size_t)b * SS_ + q0) * SS_;

    for (int kb = 0; kb < SS_ / BN; ++kb) {
        const int k0 = kb * BN;
        __syncthreads();   // previous iteration's PV (reads Ks/Vs/Es) fully done

        // ---- load K,V tiles ----
        const float* kptr = k + head_base + (size_t)k0 * DD;
        const float* vptr = v + head_base + (size_t)k0 * DD;
        #pragma unroll
        for (int t = tid; t < BN * (DD / 4); t += NTH) {
            int row = t >> 5;
            int c4  = t & 31;
            *(float4*)(Ks + row * KS_STRIDE + c4 * 4) =
                ((const float4*)(kptr + (size_t)row * DD))[c4];
            *(float4*)(Vs + row * VS_STRIDE + c4 * 4) =
                ((const float4*)(vptr + (size_t)row * DD))[c4];
        }
        __syncthreads();

        // ---- score GEMM: acc[i][j] = Q[ty*8+i] . K[tx+16*j]  (keys 0..63) ----
        float acc[8][4];
        #pragma unroll
        for (int i = 0; i < 8; i++)
            #pragma unroll
            for (int j = 0; j < 4; j++) acc[i][j] = 0.f;

        #pragma unroll 4
        for (int d = 0; d < DD; d += 4) {
            float4 kv[4];
            #pragma unroll
            for (int j = 0; j < 4; j++)
                kv[j] = *(const float4*)(Ks + (tx + 16 * j) * KS_STRIDE + d);
            #pragma unroll
            for (int i = 0; i < 8; i++) {
                float4 qv = *(const float4*)(Qs + (ty * 8 + i) * QS_STRIDE + d);
                #pragma unroll
                for (int j = 0; j < 4; j++) {
                    acc[i][j] += qv.x * kv[j].x;
                    acc[i][j] += qv.y * kv[j].y;
                    acc[i][j] += qv.z * kv[j].z;
                    acc[i][j] += qv.w * kv[j].w;
                }
            }
        }

        // ---- epilogue: mask, exp, rowsum, write unnormalized attn, stage Es ----
        #pragma unroll
        for (int i = 0; i < 8; i++) {
            const int r = ty * 8 + i;
            const int* mrow = mbase + (size_t)r * SS_ + k0;
            float* arow = attn + ((size_t)bh * SS_ + q0 + r) * SS_ + k0;
            #pragma unroll
            for (int j = 0; j < 4; j++) {
                const int c = tx + 16 * j;
                const int m = mrow[c];
                float e = (m == 0) ? 0.f : __expf(acc[i][j] * scale);
                rsum[i] += e;
                Es[c * ES_STRIDE + r] = e;
                if (write_attn) arow[c] = e;     // unnormalized; fixed by attn_norm
            }
        }
        __syncthreads();

        // ---- PV GEMM: out_acc[i][j] += sum_key Es[key][ty*8+i] * Vs[key][tx*8+j] ----
        #pragma unroll 2
        for (int key = 0; key < BN; ++key) {
            float4 ev0 = *(const float4*)(Es + key * ES_STRIDE + ty * 8);
            float4 ev1 = *(const float4*)(Es + key * ES_STRIDE + ty * 8 + 4);
            float4 vv0 = *(const float4*)(Vs + key * VS_STRIDE + tx * 8);
            float4 vv1 = *(const float4*)(Vs + key * VS_STRIDE + tx * 8 + 4);
            float ev[8] = {ev0.x, ev0.y, ev0.z, ev0.w, ev1.x, ev1.y, ev1.z, ev1.w};
            float vv[8] = {vv0.x, vv0.y, vv0.z, vv0.w, vv1.x, vv1.y, vv1.z, vv1.w};
            #pragma unroll
            for (int i = 0; i < 8; i++)
                #pragma unroll
                for (int j = 0; j < 8; j++)
                    out_acc[i][j] += ev[i] * vv[j];
        }
    }

    // ---- rowsum reduction across the 16 tx groups ----
    __syncthreads();
    #pragma unroll
    for (int i = 0; i < 8; i++)
        Red[(ty * 8 + i) * 16 + tx] = rsum[i];
    __syncthreads();
    if (tid < BM) {
        float s = 0.f;
        #pragma unroll
        for (int t = 0; t < 16; t++) s += Red[tid * 16 + t];
        float inv = 1.0f / s;
        g_inv_rowsum[(size_t)bh * SS_ + q0 + tid] = inv;
        Red[tid * 16] = inv;
    }
    __syncthreads();

    // ---- normalize + write out (cols tx*8 .. tx*8+7) ----
    #pragma unroll
    for (int i = 0; i < 8; i++) {
        const int r = ty * 8 + i;
        const float inv = Red[r * 16];
        float* orow = out + ((size_t)bh * SS_ + q0 + r) * DD + tx * 8;
        float4 o0 = make_float4(out_acc[i][0] * inv, out_acc[i][1] * inv,
                                out_acc[i][2] * inv, out_acc[i][3] * inv);
        float4 o1 = make_float4(out_acc[i][4] * inv, out_acc[i][5] * inv,
                                out_acc[i][6] * inv, out_acc[i][7] * inv);
        *(float4*)(orow)     = o0;
        *(float4*)(orow + 4) = o1;
    }
}

// Normalize attn in-place: attn[row][*] *= inv_rowsum[row]
__global__ __launch_bounds__(256)
void attn_norm(float* __restrict__ attn)
{
    const size_t total4 = (size_t)BB * HH * SS_ * SS_ / 4;
    size_t idx = (size_t)blockIdx.x * blockDim.x + threadIdx.x;
    if (idx >= total4) return;
    size_t base = idx * 4;
    size_t row = base >> 11;            // / S (=2048); all 4 elems same row
    float inv = g_inv_rowsum[row];
    float4 vv = *(float4*)(attn + base);
    vv.x *= inv; vv.y *= inv; vv.z *= inv; vv.w *= inv;
    *(float4*)(attn + base) = vv;
}

extern "C" void kernel_launch(void* const* d_in, const int* in_sizes, int n_in,
                              void* d_out, int out_size)
{
    const float* q    = (const float*)d_in[0];
    const float* k    = (const float*)d_in[1];
    const float* v    = (const float*)d_in[2];
    const int*   mask = (const int*)d_in[3];

    float* out  = (float*)d_out;
    float* attn = out + (size_t)BB * HH * SS_ * DD;

    const long long need = (long long)BB * HH * SS_ * DD + (long long)BB * HH * SS_ * SS_;
    const int write_attn = ((long long)out_size >= need) ? 1 : 0;

    size_t smem = (size_t)(BM * QS_STRIDE + BN * KS_STRIDE + BN * VS_STRIDE +
                           BN * ES_STRIDE + BM * 16) * sizeof(float);
    cudaFuncSetAttribute(attn_main, cudaFuncAttributeMaxDynamicSharedMemorySize, (int)smem);

    dim3 grid(SS_ / BM, BB * HH);
    attn_main<<<grid, NTH, smem>>>(q, k, v, mask, out, attn, write_attn);

    if (write_attn) {
        size_t total4 = (size_t)BB * HH * SS_ * SS_ / 4;
        unsigned blocks = (unsigned)((total4 + 255) / 256);
        attn_norm<<<blocks, 256>>>(attn);
    }
}

// round 4
// speedup vs baseline: 1.9873x; 1.9873x over previous
#include <cuda_runtime.h>
#include <cuda_bf16.h>
#include <cstdint>

#define BB 4
#define HH 16
#define SSEQ 2048
#define DDIM 128
#define BM 128
#define BN 64
#define NTILES (SSEQ / BN)
#define NTH 256

__device__ float g_inv_rowsum[BB * HH * SSEQ];

// smem word layout (uint32 words, each = 2 bf16)
#define QST 136            // Q/K row stride in bf16 elements (128 + 8 pad)
#define VST 72             // Vt row stride in bf16 elements (64 + 8 pad)
#define Q_HI_W 0
#define Q_LO_W (Q_HI_W + 128 * QST / 2)
#define K_HI_W (Q_LO_W + 128 * QST / 2)
#define K_LO_W (K_HI_W + 64 * QST / 2)
#define VT_HI_W (K_LO_W + 64 * QST / 2)
#define VT_LO_W (VT_HI_W + 128 * VST / 2)
#define SMEM_WORDS (VT_LO_W + 128 * VST / 2)
#define SMEM_BYTES (SMEM_WORDS * 4)

__device__ __forceinline__ void mma_bf16(float c[4],
                                         uint32_t a0, uint32_t a1, uint32_t a2, uint32_t a3,
                                         uint32_t b0, uint32_t b1)
{
    asm volatile(
        "mma.sync.aligned.m16n8k16.row.col.f32.bf16.bf16.f32 "
        "{%0,%1,%2,%3}, {%4,%5,%6,%7}, {%8,%9}, {%0,%1,%2,%3};"
        : "+f"(c[0]), "+f"(c[1]), "+f"(c[2]), "+f"(c[3])
        : "r"(a0), "r"(a1), "r"(a2), "r"(a3), "r"(b0), "r"(b1));
}

// fp32 pair -> bf16 hi/lo split, packed bf16x2 words (x in low half)
__device__ __forceinline__ void split2(float x0, float x1, uint32_t& hi, uint32_t& lo)
{
    __nv_bfloat16 h0 = __float2bfloat16(x0);
    __nv_bfloat16 h1 = __float2bfloat16(x1);
    __nv_bfloat16 l0 = __float2bfloat16(x0 - __bfloat162float(h0));
    __nv_bfloat16 l1 = __float2bfloat16(x1 - __bfloat162float(h1));
    hi = (uint32_t)__bfloat16_as_ushort(h0) | ((uint32_t)__bfloat16_as_ushort(h1) << 16);
    lo = (uint32_t)__bfloat16_as_ushort(l0) | ((uint32_t)__bfloat16_as_ushort(l1) << 16);
}

__global__ __launch_bounds__(NTH, 1)
void attn_mma(const float* __restrict__ q,
              const float* __restrict__ k,
              const float* __restrict__ v,
              const int*   __restrict__ mask,
              float* __restrict__ out,
              float* __restrict__ attn)
{
    extern __shared__ uint32_t SW[];

    const int tid  = threadIdx.x;
    const int lane = tid & 31;
    const int w16  = (tid >> 5) * 16;      // warp's 16-row slice of the 128-row block
    const int g    = lane >> 2;            // groupID 0..7
    const int tg   = lane & 3;             // thread-in-group 0..3

    const int h      = blockIdx.x;         // head (fastest -> L2 mask sharing)
    const int qblock = blockIdx.y;
    const int b      = blockIdx.z;
    const int bh     = b * HH + h;
    const int q0     = qblock * BM;
    const size_t head = (size_t)bh * SSEQ * DDIM;

    // ---- stage Q tile (128x128) as bf16 hi/lo, padded row-major ----
    {
        const float4* qp4 = (const float4*)(q + head + (size_t)q0 * DDIM);
        #pragma unroll
        for (int it = 0; it < 16; it++) {
            int idx = it * NTH + tid;              // 0..4095
            int row = idx >> 5;
            int c4  = (idx & 31) << 2;
            float4 x = qp4[idx];
            uint32_t h0, l0, h1, l1;
            split2(x.x, x.y, h0, l0);
            split2(x.z, x.w, h1, l1);
            int w = (row * QST + c4) >> 1;
            *(uint2*)(SW + Q_HI_W + w) = make_uint2(h0, h1);
            *(uint2*)(SW + Q_LO_W + w) = make_uint2(l0, l1);
        }
    }

    // accumulators
    float o[16][4];
    #pragma unroll
    for (int jn = 0; jn < 16; jn++)
        #pragma unroll
        for (int p = 0; p < 4; p++) o[jn][p] = 0.f;
    float rsum0 = 0.f, rsum1 = 0.f;

    const float scale = 0.08838834764831843f;      // 1/sqrt(128)
    const int r0 = q0 + w16 + g;                   // global q row (A frag rows r0, r0+8)
    const int* m0p = mask + ((size_t)b * SSEQ + r0) * SSEQ;
    const int* m1p = m0p + (size_t)8 * SSEQ;
    float* a0p = attn + ((size_t)bh * SSEQ + r0) * SSEQ;
    float* a1p = a0p + (size_t)8 * SSEQ;

    for (int kb = 0; kb < NTILES; kb++) {
        const int k0 = kb * BN;
        __syncthreads();                           // prior tile's MMAs done with smem

        // ---- stage K tile (64x128) bf16 hi/lo ----
        {
            const float4* kp4 = (const float4*)(k + head + (size_t)k0 * DDIM);
            #pragma unroll
            for (int it = 0; it < 8; it++) {
                int idx = it * NTH + tid;          // 0..2047
                int row = idx >> 5;
                int c4  = (idx & 31) << 2;
                float4 x = kp4[idx];
                uint32_t h0, l0, h1, l1;
                split2(x.x, x.y, h0, l0);
                split2(x.z, x.w, h1, l1);
                int w = (row * QST + c4) >> 1;
                *(uint2*)(SW + K_HI_W + w) = make_uint2(h0, h1);
                *(uint2*)(SW + K_LO_W + w) = make_uint2(l0, l1);
            }
        }
        // ---- stage V^T tile: Vt[d][key] (128x64) bf16 hi/lo ----
        {
            int d  = tid & 127;
            int kc = tid >> 7;                     // 0..1
            const float* vp = v + head + (size_t)k0 * DDIM + d;
            #pragma unroll
            for (int i = 0; i < 8; i++) {
                int kk = kc * 32 + i * 4;
                const float* p = vp + (size_t)kk * DDIM;
                float x0 = p[0], x1 = p[DDIM], x2 = p[2 * DDIM], x3 = p[3 * DDIM];
                uint32_t h0, l0, h1, l1;
                split2(x0, x1, h0, l0);
                split2(x2, x3, h1, l1);
                int w = (d * VST + kk) >> 1;
                *(uint2*)(SW + VT_HI_W + w) = make_uint2(h0, h1);
                *(uint2*)(SW + VT_LO_W + w) = make_uint2(l0, l1);
            }
        }
        __syncthreads();

        // ---- score GEMM: sc[16 rows][64 keys] via m16n8k16, 3-way bf16 split ----
        float sc[8][4];
        #pragma unroll
        for (int j = 0; j < 8; j++)
            #pragma unroll
            for (int p = 0; p < 4; p++) sc[j][p] = 0.f;

        #pragma unroll
        for (int ks = 0; ks < 8; ks++) {
            const int kc = ks * 16 + tg * 2;
            const int ra = (w16 + g) * QST;
            const int rb = (w16 + g + 8) * QST;
            uint32_t ah0 = SW[Q_HI_W + ((ra + kc) >> 1)];
            uint32_t ah1 = SW[Q_HI_W + ((rb + kc) >> 1)];
            uint32_t ah2 = SW[Q_HI_W + ((ra + kc + 8) >> 1)];
            uint32_t ah3 = SW[Q_HI_W + ((rb + kc + 8) >> 1)];
            uint32_t al0 = SW[Q_LO_W + ((ra + kc) >> 1)];
            uint32_t al1 = SW[Q_LO_W + ((rb + kc) >> 1)];
            uint32_t al2 = SW[Q_LO_W + ((ra + kc + 8) >> 1)];
            uint32_t al3 = SW[Q_LO_W + ((rb + kc + 8) >> 1)];
            #pragma unroll
            for (int j = 0; j < 8; j++) {
                const int br = (j * 8 + g) * QST;
                uint32_t bh0 = SW[K_HI_W + ((br + kc) >> 1)];
                uint32_t bh1 = SW[K_HI_W + ((br + kc + 8) >> 1)];
                uint32_t bl0 = SW[K_LO_W + ((br + kc) >> 1)];
                uint32_t bl1 = SW[K_LO_W + ((br + kc + 8) >> 1)];
                mma_bf16(sc[j], ah0, ah1, ah2, ah3, bh0, bh1);
                mma_bf16(sc[j], ah0, ah1, ah2, ah3, bl0, bl1);
                mma_bf16(sc[j], al0, al1, al2, al3, bh0, bh1);
            }
        }

        // ---- epilogue: mask + exp, write unnormalized attn, pack e -> bf16 hi/lo ----
        uint32_t eh[16], el[16];
        #pragma unroll
        for (int j = 0; j < 8; j++) {
            const int c = k0 + tg * 2 + j * 8;
            int2 m0 = *(const int2*)(m0p + c);
            int2 m1 = *(const int2*)(m1p + c);
            float e00 = m0.x ? __expf(sc[j][0] * scale) : 0.f;
            float e01 = m0.y ? __expf(sc[j][1] * scale) : 0.f;
            float e10 = m1.x ? __expf(sc[j][2] * scale) : 0.f;
            float e11 = m1.y ? __expf(sc[j][3] * scale) : 0.f;
            *(float2*)(a0p + c) = make_float2(e00, e01);
            *(float2*)(a1p + c) = make_float2(e10, e11);
            rsum0 += e00 + e01;
            rsum1 += e10 + e11;
            split2(e00, e01, eh[j * 2], el[j * 2]);
            split2(e10, e11, eh[j * 2 + 1], el[j * 2 + 1]);
        }

        // ---- PV GEMM: o[16 rows][128 d] += e[16x64] * V[64x128], 3-way split ----
        // score C fragment layout == PV A fragment layout: no smem round-trip.
        #pragma unroll
        for (int ks = 0; ks < 4; ks++) {
            uint32_t ah0 = eh[ks * 4 + 0], ah1 = eh[ks * 4 + 1];
            uint32_t ah2 = eh[ks * 4 + 2], ah3 = eh[ks * 4 + 3];
            uint32_t al0 = el[ks * 4 + 0], al1 = el[ks * 4 + 1];
            uint32_t al2 = el[ks * 4 + 2], al3 = el[ks * 4 + 3];
            const int kcc = ks * 16 + tg * 2;
            #pragma unroll
            for (int jn = 0; jn < 16; jn++) {
                const int br = (jn * 8 + g) * VST;
                uint32_t bh0 = SW[VT_HI_W + ((br + kcc) >> 1)];
                uint32_t bh1 = SW[VT_HI_W + ((br + kcc + 8) >> 1)];
                uint32_t bl0 = SW[VT_LO_W + ((br + kcc) >> 1)];
                uint32_t bl1 = SW[VT_LO_W + ((br + kcc + 8) >> 1)];
                mma_bf16(o[jn], ah0, ah1, ah2, ah3, bh0, bh1);
                mma_bf16(o[jn], ah0, ah1, ah2, ah3, bl0, bl1);
                mma_bf16(o[jn], al0, al1, al2, al3, bh0, bh1);
            }
        }
    }

    // ---- rowsum butterfly within each 4-lane quad (rows owned per-warp) ----
    rsum0 += __shfl_xor_sync(0xFFFFFFFF, rsum0, 1);
    rsum0 += __shfl_xor_sync(0xFFFFFFFF, rsum0, 2);
    rsum1 += __shfl_xor_sync(0xFFFFFFFF, rsum1, 1);
    rsum1 += __shfl_xor_sync(0xFFFFFFFF, rsum1, 2);
    const float inv0 = 1.0f / rsum0;
    const float inv1 = 1.0f / rsum1;
    if (tg == 0) {
        g_inv_rowsum[(size_t)bh * SSEQ + r0]     = inv0;
        g_inv_rowsum[(size_t)bh * SSEQ + r0 + 8] = inv1;
    }

    // ---- normalized out ----
    float* o0p = out + ((size_t)bh * SSEQ + r0) * DDIM;
    float* o1p = o0p + (size_t)8 * DDIM;
    #pragma unroll
    for (int jn = 0; jn < 16; jn++) {
        const int c = jn * 8 + tg * 2;
        *(float2*)(o0p + c) = make_float2(o[jn][0] * inv0, o[jn][1] * inv0);
        *(float2*)(o1p + c) = make_float2(o[jn][2] * inv1, o[jn][3] * inv1);
    }
}

// Normalize attn in-place: attn[row][*] *= inv_rowsum[row]
__global__ __launch_bounds__(256)
void attn_norm(float* __restrict__ attn)
{
    const size_t total4 = (size_t)BB * HH * SSEQ * SSEQ / 4;
    size_t idx = (size_t)blockIdx.x * blockDim.x + threadIdx.x;
    if (idx >= total4) return;
    size_t base = idx * 4;
    size_t row = base >> 11;            // / S (=2048)
    float inv = g_inv_rowsum[row];
    float4 vv = *(float4*)(attn + base);
    vv.x *= inv; vv.y *= inv; vv.z *= inv; vv.w *= inv;
    *(float4*)(attn + base) = vv;
}

extern "C" void kernel_launch(void* const* d_in, const int* in_sizes, int n_in,
                              void* d_out, int out_size)
{
    const float* q    = (const float*)d_in[0];
    const float* k    = (const float*)d_in[1];
    const float* v    = (const float*)d_in[2];
    const int*   mask = (const int*)d_in[3];

    float* out  = (float*)d_out;
    float* attn = out + (size_t)BB * HH * SSEQ * DDIM;

    cudaFuncSetAttribute(attn_mma, cudaFuncAttributeMaxDynamicSharedMemorySize, SMEM_BYTES);

    dim3 grid(HH, SSEQ / BM, BB);       // h fastest: concurrent CTAs share mask + K/V in L2
    attn_mma<<<grid, NTH, SMEM_BYTES>>>(q, k, v, mask, out, attn);

    size_t total4 = (size_t)BB * HH * SSEQ * SSEQ / 4;
    unsigned blocks = (unsigned)((total4 + 255) / 256);
    attn_norm<<<blocks, 256>>>(attn);
}

// round 5
// speedup vs baseline: 2.2062x; 1.1101x over previous
#include <cuda_runtime.h>
#include <cuda_bf16.h>
#include <cstdint>

#define BB 4
#define HH 16
#define SSEQ 2048
#define DDIM 128
#define BM 128
#define BN 64
#define NTILES (SSEQ / BN)
#define NTH 256

__device__ float g_inv_rowsum[BB * HH * SSEQ];

// smem word layout (uint32 words, each = 2 bf16). Row stride 136 bf16 = 272 B:
// 16B-aligned rows, odd 16B-unit stride -> conflict-free ldmatrix.
#define QST 136
#define QROWW 68                       // words per row
#define Q_HI_W 0
#define Q_LO_W (128 * QROWW)           // 8704
#define KBUF_HI_W(buf) (17408 + (buf) * 8704)
#define KBUF_LO_W(buf) (KBUF_HI_W(buf) + 4352)
#define VBUF_HI_W(buf) (34816 + (buf) * 8704)
#define VBUF_LO_W(buf) (VBUF_HI_W(buf) + 4352)
#define SMEM_WORDS 52224
#define SMEM_BYTES (SMEM_WORDS * 4)    // 208,896 B

__device__ __forceinline__ uint32_t smem_u32(const void* p) {
    uint32_t a;
    asm("{ .reg .u64 t; cvta.to.shared.u64 t, %1; cvt.u32.u64 %0, t; }" : "=r"(a) : "l"(p));
    return a;
}

__device__ __forceinline__ void mma_bf16(float c[4],
                                         uint32_t a0, uint32_t a1, uint32_t a2, uint32_t a3,
                                         uint32_t b0, uint32_t b1)
{
    asm volatile(
        "mma.sync.aligned.m16n8k16.row.col.f32.bf16.bf16.f32 "
        "{%0,%1,%2,%3}, {%4,%5,%6,%7}, {%8,%9}, {%0,%1,%2,%3};"
        : "+f"(c[0]), "+f"(c[1]), "+f"(c[2]), "+f"(c[3])
        : "r"(a0), "r"(a1), "r"(a2), "r"(a3), "r"(b0), "r"(b1));
}

__device__ __forceinline__ void ldsm4(uint32_t& r0, uint32_t& r1, uint32_t& r2, uint32_t& r3,
                                      uint32_t saddr)
{
    asm volatile("ldmatrix.sync.aligned.m8n8.x4.shared.b16 {%0,%1,%2,%3}, [%4];"
                 : "=r"(r0), "=r"(r1), "=r"(r2), "=r"(r3) : "r"(saddr));
}
__device__ __forceinline__ void ldsm4t(uint32_t& r0, uint32_t& r1, uint32_t& r2, uint32_t& r3,
                                       uint32_t saddr)
{
    asm volatile("ldmatrix.sync.aligned.m8n8.x4.trans.shared.b16 {%0,%1,%2,%3}, [%4];"
                 : "=r"(r0), "=r"(r1), "=r"(r2), "=r"(r3) : "r"(saddr));
}

// fp32 pair -> bf16 hi/lo split, packed bf16x2 (x0 in low half)
__device__ __forceinline__ void split2(float x0, float x1, uint32_t& hi, uint32_t& lo)
{
    __nv_bfloat162 h = __floats2bfloat162_rn(x0, x1);
    float2 hf = __bfloat1622float2(h);
    __nv_bfloat162 l = __floats2bfloat162_rn(x0 - hf.x, x1 - hf.y);
    hi = *reinterpret_cast<uint32_t*>(&h);
    lo = *reinterpret_cast<uint32_t*>(&l);
}

// stage one 64x128 fp32 tile -> bf16 hi/lo padded smem (rows = keys, coalesced)
__device__ __forceinline__ void stage_tile(const float4* kp4, const float4* vp4,
                                           uint32_t* SW, int buf, int tid)
{
    uint32_t* khi = SW + KBUF_HI_W(buf);
    uint32_t* klo = SW + KBUF_LO_W(buf);
    uint32_t* vhi = SW + VBUF_HI_W(buf);
    uint32_t* vlo = SW + VBUF_LO_W(buf);
    #pragma unroll
    for (int it = 0; it < 8; it++) {
        int idx = it * NTH + tid;          // 0..2047 float4s
        int row = idx >> 5;
        int c4  = (idx & 31) << 2;
        int w   = (row * QST + c4) >> 1;
        float4 x = kp4[idx];
        uint32_t h0, l0, h1, l1;
        split2(x.x, x.y, h0, l0);
        split2(x.z, x.w, h1, l1);
        *(uint2*)(khi + w) = make_uint2(h0, h1);
        *(uint2*)(klo + w) = make_uint2(l0, l1);
        float4 y = vp4[idx];
        split2(y.x, y.y, h0, l0);
        split2(y.z, y.w, h1, l1);
        *(uint2*)(vhi + w) = make_uint2(h0, h1);
        *(uint2*)(vlo + w) = make_uint2(l0, l1);
    }
}

__global__ __launch_bounds__(NTH, 1)
void attn_mma(const float* __restrict__ q,
              const float* __restrict__ k,
              const float* __restrict__ v,
              const int*   __restrict__ mask,
              float* __restrict__ out,
              float* __restrict__ attn)
{
    extern __shared__ uint32_t SW[];
    const uint32_t sb = smem_u32(SW);

    const int tid  = threadIdx.x;
    const int lane = tid & 31;
    const int w16  = (tid >> 5) * 16;      // warp's 16-row slice
    const int g    = lane >> 2;
    const int tg   = lane & 3;

    const int h      = blockIdx.x;
    const int qblock = blockIdx.y;
    const int b      = blockIdx.z;
    const int bh     = b * HH + h;
    const int q0     = qblock * BM;
    const size_t head = (size_t)bh * SSEQ * DDIM;

    // ---- stage Q tile (128x128) bf16 hi/lo ----
    {
        const float4* qp4 = (const float4*)(q + head + (size_t)q0 * DDIM);
        #pragma unroll
        for (int it = 0; it < 16; it++) {
            int idx = it * NTH + tid;
            int row = idx >> 5;
            int c4  = (idx & 31) << 2;
            float4 x = qp4[idx];
            uint32_t h0, l0, h1, l1;
            split2(x.x, x.y, h0, l0);
            split2(x.z, x.w, h1, l1);
            int w = (row * QST + c4) >> 1;
            *(uint2*)(SW + Q_HI_W + w) = make_uint2(h0, h1);
            *(uint2*)(SW + Q_LO_W + w) = make_uint2(l0, l1);
        }
    }
    // stage K/V tile 0 into buffer 0
    stage_tile((const float4*)(k + head), (const float4*)(v + head), SW, 0, tid);

    // ldmatrix lane-address bases (byte offsets within a tile)
    const uint32_t a_byte  = (uint32_t)(((w16 + (lane & 15)) * QST + ((lane & 16) ? 8 : 0)) * 2);
    const uint32_t qhi_ad  = sb + Q_HI_W * 4 + a_byte;
    const uint32_t qlo_ad  = sb + Q_LO_W * 4 + a_byte;
    const uint32_t bk_byte = (uint32_t)((((lane & 7) + ((lane & 16) ? 8 : 0)) * QST +
                                         ((lane & 8) ? 8 : 0)) * 2);
    const uint32_t bv_byte = (uint32_t)((((lane & 7) + ((lane & 8) ? 8 : 0)) * QST) * 2 +
                                        ((lane & 16) ? 16 : 0));

    // accumulators
    float o[16][4];
    #pragma unroll
    for (int jn = 0; jn < 16; jn++)
        #pragma unroll
        for (int p = 0; p < 4; p++) o[jn][p] = 0.f;
    float rsum0 = 0.f, rsum1 = 0.f;

    const float scale = 0.08838834764831843f;   // 1/sqrt(128)
    const int r0 = q0 + w16 + g;
    const int* m0p = mask + ((size_t)b * SSEQ + r0) * SSEQ;
    const int* m1p = m0p + (size_t)8 * SSEQ;
    float* a0p = attn + ((size_t)bh * SSEQ + r0) * SSEQ;
    float* a1p = a0p + (size_t)8 * SSEQ;

    __syncthreads();

    for (int kb = 0; kb < NTILES; kb++) {
        const int buf = kb & 1;
        const int k0  = kb * BN;

        // prefetch next tile into the other buffer (overlaps with MMAs below)
        if (kb + 1 < NTILES) {
            const size_t nk0 = (size_t)(k0 + BN) * DDIM;
            stage_tile((const float4*)(k + head + nk0),
                       (const float4*)(v + head + nk0), SW, buf ^ 1, tid);
        }

        const uint32_t khi_ad = sb + KBUF_HI_W(buf) * 4 + bk_byte;
        const uint32_t klo_ad = sb + KBUF_LO_W(buf) * 4 + bk_byte;
        const uint32_t vhi_ad = sb + VBUF_HI_W(buf) * 4 + bv_byte;
        const uint32_t vlo_ad = sb + VBUF_LO_W(buf) * 4 + bv_byte;

        // ---- score GEMM: sc[16][64] = Q K^T, 3-way bf16 split ----
        float sc[8][4];
        #pragma unroll
        for (int j = 0; j < 8; j++)
            #pragma unroll
            for (int p = 0; p < 4; p++) sc[j][p] = 0.f;

        #pragma unroll
        for (int ks = 0; ks < 8; ks++) {
            uint32_t ah0, ah1, ah2, ah3, al0, al1, al2, al3;
            ldsm4(ah0, ah1, ah2, ah3, qhi_ad + ks * 32);
            ldsm4(al0, al1, al2, al3, qlo_ad + ks * 32);
            #pragma unroll
            for (int jp = 0; jp < 4; jp++) {
                uint32_t b0, b1, b2, b3, c0, c1, c2, c3;
                ldsm4(b0, b1, b2, b3, khi_ad + ks * 32 + jp * (16 * QST * 2));
                ldsm4(c0, c1, c2, c3, klo_ad + ks * 32 + jp * (16 * QST * 2));
                mma_bf16(sc[2 * jp],     ah0, ah1, ah2, ah3, b0, b1);
                mma_bf16(sc[2 * jp],     ah0, ah1, ah2, ah3, c0, c1);
                mma_bf16(sc[2 * jp],     al0, al1, al2, al3, b0, b1);
                mma_bf16(sc[2 * jp + 1], ah0, ah1, ah2, ah3, b2, b3);
                mma_bf16(sc[2 * jp + 1], ah0, ah1, ah2, ah3, c2, c3);
                mma_bf16(sc[2 * jp + 1], al0, al1, al2, al3, b2, b3);
            }
        }

        // ---- epilogue: mask + exp, write unnormalized attn, pack e hi/lo ----
        uint32_t eh[16], el[16];
        #pragma unroll
        for (int j = 0; j < 8; j++) {
            const int c = k0 + tg * 2 + j * 8;
            int2 m0 = *(const int2*)(m0p + c);
            int2 m1 = *(const int2*)(m1p + c);
            float e00 = m0.x ? __expf(sc[j][0] * scale) : 0.f;
            float e01 = m0.y ? __expf(sc[j][1] * scale) : 0.f;
            float e10 = m1.x ? __expf(sc[j][2] * scale) : 0.f;
            float e11 = m1.y ? __expf(sc[j][3] * scale) : 0.f;
            *(float2*)(a0p + c) = make_float2(e00, e01);
            *(float2*)(a1p + c) = make_float2(e10, e11);
            rsum0 += e00 + e01;
            rsum1 += e10 + e11;
            split2(e00, e01, eh[j * 2], el[j * 2]);
            split2(e10, e11, eh[j * 2 + 1], el[j * 2 + 1]);
        }

        // ---- PV GEMM: o[16][128] += e[16x64] * V[64x128], 3-way split ----
        #pragma unroll
        for (int ks = 0; ks < 4; ks++) {
            uint32_t ah0 = eh[ks * 4 + 0], ah1 = eh[ks * 4 + 1];
            uint32_t ah2 = eh[ks * 4 + 2], ah3 = eh[ks * 4 + 3];
            uint32_t al0 = el[ks * 4 + 0], al1 = el[ks * 4 + 1];
            uint32_t al2 = el[ks * 4 + 2], al3 = el[ks * 4 + 3];
            #pragma unroll
            for (int jnp = 0; jnp < 8; jnp++) {
                uint32_t b0, b1, b2, b3, c0, c1, c2, c3;
                ldsm4t(b0, b1, b2, b3, vhi_ad + ks * (16 * QST * 2) + jnp * 32);
                ldsm4t(c0, c1, c2, c3, vlo_ad + ks * (16 * QST * 2) + jnp * 32);
                mma_bf16(o[2 * jnp],     ah0, ah1, ah2, ah3, b0, b1);
                mma_bf16(o[2 * jnp],     ah0, ah1, ah2, ah3, c0, c1);
                mma_bf16(o[2 * jnp],     al0, al1, al2, al3, b0, b1);
                mma_bf16(o[2 * jnp + 1], ah0, ah1, ah2, ah3, b2, b3);
                mma_bf16(o[2 * jnp + 1], ah0, ah1, ah2, ah3, c2, c3);
                mma_bf16(o[2 * jnp + 1], al0, al1, al2, al3, b2, b3);
            }
        }

        __syncthreads();   // next-tile staging visible; this buf free for kb+2 staging
    }

    // ---- rowsum butterfly within each 4-lane quad ----
    rsum0 += __shfl_xor_sync(0xFFFFFFFF, rsum0, 1);
    rsum0 += __shfl_xor_sync(0xFFFFFFFF, rsum0, 2);
    rsum1 += __shfl_xor_sync(0xFFFFFFFF, rsum1, 1);
    rsum1 += __shfl_xor_sync(0xFFFFFFFF, rsum1, 2);
    const float inv0 = 1.0f / rsum0;
    const float inv1 = 1.0f / rsum1;
    if (tg == 0) {
        g_inv_rowsum[(size_t)bh * SSEQ + r0]     = inv0;
        g_inv_rowsum[(size_t)bh * SSEQ + r0 + 8] = inv1;
    }

    // ---- normalized out ----
    float* o0p = out + ((size_t)bh * SSEQ + r0) * DDIM;
    float* o1p = o0p + (size_t)8 * DDIM;
    #pragma unroll
    for (int jn = 0; jn < 16; jn++) {
        const int c = jn * 8 + tg * 2;
        *(float2*)(o0p + c) = make_float2(o[jn][0] * inv0, o[jn][1] * inv0);
        *(float2*)(o1p + c) = make_float2(o[jn][2] * inv1, o[jn][3] * inv1);
    }
}

// Normalize attn in-place: attn[row][*] *= inv_rowsum[row]
__global__ __launch_bounds__(256)
void attn_norm(float* __restrict__ attn)
{
    const size_t total4 = (size_t)BB * HH * SSEQ * SSEQ / 4;
    size_t idx = (size_t)blockIdx.x * blockDim.x + threadIdx.x;
    if (idx >= total4) return;
    size_t base = idx * 4;
    size_t row = base >> 11;
    float inv = g_inv_rowsum[row];
    float4 vv = *(float4*)(attn + base);
    vv.x *= inv; vv.y *= inv; vv.z *= inv; vv.w *= inv;
    *(float4*)(attn + base) = vv;
}

extern "C" void kernel_launch(void* const* d_in, const int* in_sizes, int n_in,
                              void* d_out, int out_size)
{
    const float* q    = (const float*)d_in[0];
    const float* k    = (const float*)d_in[1];
    const float* v    = (const float*)d_in[2];
    const int*   mask = (const int*)d_in[3];

    float* out  = (float*)d_out;
    float* attn = out + (size_t)BB * HH * SSEQ * DDIM;

    cudaFuncSetAttribute(attn_mma, cudaFuncAttributeMaxDynamicSharedMemorySize, SMEM_BYTES);

    dim3 grid(HH, SSEQ / BM, BB);       // h fastest: concurrent CTAs share mask + K/V in L2
    attn_mma<<<grid, NTH, SMEM_BYTES>>>(q, k, v, mask, out, attn);

    size_t total4 = (size_t)BB * HH * SSEQ * SSEQ / 4;
    unsigned blocks = (unsigned)((total4 + 255) / 256);
    attn_norm<<<blocks, 256>>>(attn);
}

// round 6
// speedup vs baseline: 2.4132x; 1.0938x over previous
#include <cuda_runtime.h>
#include <cuda_bf16.h>
#include <cstdint>

#define BB 4
#define HH 16
#define SSEQ 2048
#define DDIM 128
#define BM 128
#define BN 64
#define NTILES (SSEQ / BN)
#define NTH 256

__device__ float g_inv_rowsum[BB * HH * SSEQ];

// smem word layout (uint32 words, each = 2 bf16). Row stride 136 bf16 = 272 B.
#define QST 136
#define QROWW 68
#define Q_HI_W 0
#define Q_LO_W (128 * QROWW)
#define KBUF_HI_W(buf) (17408 + (buf) * 8704)
#define KBUF_LO_W(buf) (KBUF_HI_W(buf) + 4352)
#define VBUF_HI_W(buf) (34816 + (buf) * 8704)
#define VBUF_LO_W(buf) (VBUF_HI_W(buf) + 4352)
#define SMEM_WORDS 52224
#define SMEM_BYTES (SMEM_WORDS * 4)    // 208,896 B

__device__ __forceinline__ uint32_t smem_u32(const void* p) {
    uint32_t a;
    asm("{ .reg .u64 t; cvta.to.shared.u64 t, %1; cvt.u32.u64 %0, t; }" : "=r"(a) : "l"(p));
    return a;
}

__device__ __forceinline__ void mma_bf16(float c[4],
                                         uint32_t a0, uint32_t a1, uint32_t a2, uint32_t a3,
                                         uint32_t b0, uint32_t b1)
{
    asm volatile(
        "mma.sync.aligned.m16n8k16.row.col.f32.bf16.bf16.f32 "
        "{%0,%1,%2,%3}, {%4,%5,%6,%7}, {%8,%9}, {%0,%1,%2,%3};"
        : "+f"(c[0]), "+f"(c[1]), "+f"(c[2]), "+f"(c[3])
        : "r"(a0), "r"(a1), "r"(a2), "r"(a3), "r"(b0), "r"(b1));
}

__device__ __forceinline__ void ldsm4(uint32_t& r0, uint32_t& r1, uint32_t& r2, uint32_t& r3,
                                      uint32_t saddr)
{
    asm volatile("ldmatrix.sync.aligned.m8n8.x4.shared.b16 {%0,%1,%2,%3}, [%4];"
                 : "=r"(r0), "=r"(r1), "=r"(r2), "=r"(r3) : "r"(saddr));
}
__device__ __forceinline__ void ldsm4t(uint32_t& r0, uint32_t& r1, uint32_t& r2, uint32_t& r3,
                                       uint32_t saddr)
{
    asm volatile("ldmatrix.sync.aligned.m8n8.x4.trans.shared.b16 {%0,%1,%2,%3}, [%4];"
                 : "=r"(r0), "=r"(r1), "=r"(r2), "=r"(r3) : "r"(saddr));
}

// fp32 pair -> bf16 hi/lo split, packed bf16x2 (x0 in low half)
__device__ __forceinline__ void split2(float x0, float x1, uint32_t& hi, uint32_t& lo)
{
    __nv_bfloat162 h = __floats2bfloat162_rn(x0, x1);
    float2 hf = __bfloat1622float2(h);
    __nv_bfloat162 l = __floats2bfloat162_rn(x0 - hf.x, x1 - hf.y);
    hi = *reinterpret_cast<uint32_t*>(&h);
    lo = *reinterpret_cast<uint32_t*>(&l);
}

// register-resident staging halves: 8 float4 per thread = one 64x128 fp32 tile per CTA
__device__ __forceinline__ void load8(const float4* p4, int tid, float4 r[8])
{
    #pragma unroll
    for (int it = 0; it < 8; it++) r[it] = p4[it * NTH + tid];
}
__device__ __forceinline__ void store8(const float4 r[8], uint32_t* hi, uint32_t* lo, int tid)
{
    #pragma unroll
    for (int it = 0; it < 8; it++) {
        int idx = it * NTH + tid;
        int row = idx >> 5;
        int c4  = (idx & 31) << 2;
        int w   = (row * QST + c4) >> 1;
        uint32_t h0, l0, h1, l1;
        split2(r[it].x, r[it].y, h0, l0);
        split2(r[it].z, r[it].w, h1, l1);
        *(uint2*)(hi + w) = make_uint2(h0, h1);
        *(uint2*)(lo + w) = make_uint2(l0, l1);
    }
}

__global__ __launch_bounds__(NTH, 1)
void attn_mma(const float* __restrict__ q,
              const float* __restrict__ k,
              const float* __restrict__ v,
              const int*   __restrict__ mask,
              float* __restrict__ out,
              float* __restrict__ attn)
{
    extern __shared__ uint32_t SW[];
    const uint32_t sb = smem_u32(SW);

    const int tid  = threadIdx.x;
    const int lane = tid & 31;
    const int w16  = (tid >> 5) * 16;
    const int g    = lane >> 2;
    const int tg   = lane & 3;

    const int h      = blockIdx.x;
    const int qblock = blockIdx.y;
    const int b      = blockIdx.z;
    const int bh     = b * HH + h;
    const int q0     = qblock * BM;
    const size_t head = (size_t)bh * SSEQ * DDIM;

    // ---- stage Q tile (128x128) bf16 hi/lo ----
    {
        const float4* qp4 = (const float4*)(q + head + (size_t)q0 * DDIM);
        #pragma unroll
        for (int it = 0; it < 16; it++) {
            int idx = it * NTH + tid;
            int row = idx >> 5;
            int c4  = (idx & 31) << 2;
            float4 x = qp4[idx];
            uint32_t h0, l0, h1, l1;
            split2(x.x, x.y, h0, l0);
            split2(x.z, x.w, h1, l1);
            int w = (row * QST + c4) >> 1;
            *(uint2*)(SW + Q_HI_W + w) = make_uint2(h0, h1);
            *(uint2*)(SW + Q_LO_W + w) = make_uint2(l0, l1);
        }
    }
    // stage K/V tile 0 into buffer 0
    {
        float4 r[8];
        load8((const float4*)(k + head), tid, r);
        store8(r, SW + KBUF_HI_W(0), SW + KBUF_LO_W(0), tid);
        load8((const float4*)(v + head), tid, r);
        store8(r, SW + VBUF_HI_W(0), SW + VBUF_LO_W(0), tid);
    }

    // ldmatrix lane-address bases (byte offsets within a tile)
    const uint32_t a_byte  = (uint32_t)(((w16 + (lane & 15)) * QST + ((lane & 16) ? 8 : 0)) * 2);
    const uint32_t qhi_ad  = sb + Q_HI_W * 4 + a_byte;
    const uint32_t qlo_ad  = sb + Q_LO_W * 4 + a_byte;
    const uint32_t bk_byte = (uint32_t)((((lane & 7) + ((lane & 16) ? 8 : 0)) * QST +
                                         ((lane & 8) ? 8 : 0)) * 2);
    const uint32_t bv_byte = (uint32_t)((((lane & 7) + ((lane & 8) ? 8 : 0)) * QST) * 2 +
                                        ((lane & 16) ? 16 : 0));

    // accumulators
    float o[16][4];
    #pragma unroll
    for (int jn = 0; jn < 16; jn++)
        #pragma unroll
        for (int p = 0; p < 4; p++) o[jn][p] = 0.f;
    float rsum0 = 0.f, rsum1 = 0.f;

    const float scale = 0.08838834764831843f;   // 1/sqrt(128)
    const int r0 = q0 + w16 + g;
    const int* m0p = mask + ((size_t)b * SSEQ + r0) * SSEQ;
    const int* m1p = m0p + (size_t)8 * SSEQ;
    float* a0p = attn + ((size_t)bh * SSEQ + r0) * SSEQ;
    float* a1p = a0p + (size_t)8 * SSEQ;

    __syncthreads();

    for (int kb = 0; kb < NTILES; kb++) {
        const int buf = kb & 1;
        const int k0  = kb * BN;
        const bool pf = (kb + 1 < NTILES);
        const size_t nk0 = (size_t)(k0 + BN) * DDIM;

        // ---- issue next-tile K loads now; consumed AFTER score MMAs ----
        float4 streg[8];
        if (pf) load8((const float4*)(k + head + nk0), tid, streg);

        const uint32_t khi_ad = sb + KBUF_HI_W(buf) * 4 + bk_byte;
        const uint32_t klo_ad = sb + KBUF_LO_W(buf) * 4 + bk_byte;
        const uint32_t vhi_ad = sb + VBUF_HI_W(buf) * 4 + bv_byte;
        const uint32_t vlo_ad = sb + VBUF_LO_W(buf) * 4 + bv_byte;

        // ---- score GEMM: sc[16][64] = Q K^T, 3-way bf16 split ----
        float sc[8][4];
        #pragma unroll
        for (int j = 0; j < 8; j++)
            #pragma unroll
            for (int p = 0; p < 4; p++) sc[j][p] = 0.f;

        #pragma unroll
        for (int ks = 0; ks < 8; ks++) {
            uint32_t ah0, ah1, ah2, ah3, al0, al1, al2, al3;
            ldsm4(ah0, ah1, ah2, ah3, qhi_ad + ks * 32);
            ldsm4(al0, al1, al2, al3, qlo_ad + ks * 32);
            #pragma unroll
            for (int jp = 0; jp < 4; jp++) {
                uint32_t b0, b1, b2, b3, c0, c1, c2, c3;
                ldsm4(b0, b1, b2, b3, khi_ad + ks * 32 + jp * (16 * QST * 2));
                ldsm4(c0, c1, c2, c3, klo_ad + ks * 32 + jp * (16 * QST * 2));
                mma_bf16(sc[2 * jp],     ah0, ah1, ah2, ah3, b0, b1);
                mma_bf16(sc[2 * jp],     ah0, ah1, ah2, ah3, c0, c1);
                mma_bf16(sc[2 * jp],     al0, al1, al2, al3, b0, b1);
                mma_bf16(sc[2 * jp + 1], ah0, ah1, ah2, ah3, b2, b3);
                mma_bf16(sc[2 * jp + 1], ah0, ah1, ah2, ah3, c2, c3);
                mma_bf16(sc[2 * jp + 1], al0, al1, al2, al3, b2, b3);
            }
        }

        // ---- K(next): convert + store to other buffer (LDG latency now hidden) ----
        if (pf) store8(streg, SW + KBUF_HI_W(buf ^ 1), SW + KBUF_LO_W(buf ^ 1), tid);

        // ---- epilogue: mask + exp, write unnormalized attn, pack e hi/lo ----
        uint32_t eh[16], el[16];
        #pragma unroll
        for (int j = 0; j < 8; j++) {
            const int c = k0 + tg * 2 + j * 8;
            int2 m0 = *(const int2*)(m0p + c);
            int2 m1 = *(const int2*)(m1p + c);
            float e00 = m0.x ? __expf(sc[j][0] * scale) : 0.f;
            float e01 = m0.y ? __expf(sc[j][1] * scale) : 0.f;
            float e10 = m1.x ? __expf(sc[j][2] * scale) : 0.f;
            float e11 = m1.y ? __expf(sc[j][3] * scale) : 0.f;
            *(float2*)(a0p + c) = make_float2(e00, e01);
            *(float2*)(a1p + c) = make_float2(e10, e11);
            rsum0 += e00 + e01;
            rsum1 += e10 + e11;
            split2(e00, e01, eh[j * 2], el[j * 2]);
            split2(e10, e11, eh[j * 2 + 1], el[j * 2 + 1]);
        }

        // ---- issue next-tile V loads now; consumed AFTER PV MMAs ----
        if (pf) load8((const float4*)(v + head + nk0), tid, streg);

        // ---- PV GEMM: o[16][128] += e[16x64] * V[64x128], 3-way split ----
        #pragma unroll
        for (int ks = 0; ks < 4; ks++) {
            uint32_t ah0 = eh[ks * 4 + 0], ah1 = eh[ks * 4 + 1];
            uint32_t ah2 = eh[ks * 4 + 2], ah3 = eh[ks * 4 + 3];
            uint32_t al0 = el[ks * 4 + 0], al1 = el[ks * 4 + 1];
            uint32_t al2 = el[ks * 4 + 2], al3 = el[ks * 4 + 3];
            #pragma unroll
            for (int jnp = 0; jnp < 8; jnp++) {
                uint32_t b0, b1, b2, b3, c0, c1, c2, c3;
                ldsm4t(b0, b1, b2, b3, vhi_ad + ks * (16 * QST * 2) + jnp * 32);
                ldsm4t(c0, c1, c2, c3, vlo_ad + ks * (16 * QST * 2) + jnp * 32);
                mma_bf16(o[2 * jnp],     ah0, ah1, ah2, ah3, b0, b1);
                mma_bf16(o[2 * jnp],     ah0, ah1, ah2, ah3, c0, c1);
                mma_bf16(o[2 * jnp],     al0, al1, al2, al3, b0, b1);
                mma_bf16(o[2 * jnp + 1], ah0, ah1, ah2, ah3, b2, b3);
                mma_bf16(o[2 * jnp + 1], ah0, ah1, ah2, ah3, c2, c3);
                mma_bf16(o[2 * jnp + 1], al0, al1, al2, al3, b2, b3);
            }
        }

        // ---- V(next): convert + store (LDG latency hidden behind PV) ----
        if (pf) store8(streg, SW + VBUF_HI_W(buf ^ 1), SW + VBUF_LO_W(buf ^ 1), tid);

        __syncthreads();
    }

    // ---- rowsum butterfly within each 4-lane quad ----
    rsum0 += __shfl_xor_sync(0xFFFFFFFF, rsum0, 1);
    rsum0 += __shfl_xor_sync(0xFFFFFFFF, rsum0, 2);
    rsum1 += __shfl_xor_sync(0xFFFFFFFF, rsum1, 1);
    rsum1 += __shfl_xor_sync(0xFFFFFFFF, rsum1, 2);
    const float inv0 = 1.0f / rsum0;
    const float inv1 = 1.0f / rsum1;
    if (tg == 0) {
        g_inv_rowsum[(size_t)bh * SSEQ + r0]     = inv0;
        g_inv_rowsum[(size_t)bh * SSEQ + r0 + 8] = inv1;
    }

    // ---- normalized out ----
    float* o0p = out + ((size_t)bh * SSEQ + r0) * DDIM;
    float* o1p = o0p + (size_t)8 * DDIM;
    #pragma unroll
    for (int jn = 0; jn < 16; jn++) {
        const int c = jn * 8 + tg * 2;
        *(float2*)(o0p + c) = make_float2(o[jn][0] * inv0, o[jn][1] * inv0);
        *(float2*)(o1p + c) = make_float2(o[jn][2] * inv1, o[jn][3] * inv1);
    }
}

// Normalize attn in-place: attn[row][*] *= inv_rowsum[row]
__global__ __launch_bounds__(256)
void attn_norm(float* __restrict__ attn)
{
    const size_t total4 = (size_t)BB * HH * SSEQ * SSEQ / 4;
    size_t idx = (size_t)blockIdx.x * blockDim.x + threadIdx.x;
    if (idx >= total4) return;
    size_t base = idx * 4;
    size_t row = base >> 11;
    float inv = g_inv_rowsum[row];
    float4 vv = *(float4*)(attn + base);
    vv.x *= inv; vv.y *= inv; vv.z *= inv; vv.w *= inv;
    *(float4*)(attn + base) = vv;
}

extern "C" void kernel_launch(void* const* d_in, const int* in_sizes, int n_in,
                              void* d_out, int out_size)
{
    const float* q    = (const float*)d_in[0];
    const float* k    = (const float*)d_in[1];
    const float* v    = (const float*)d_in[2];
    const int*   mask = (const int*)d_in[3];

    float* out  = (float*)d_out;
    float* attn = out + (size_t)BB * HH * SSEQ * DDIM;

    cudaFuncSetAttribute(attn_mma, cudaFuncAttributeMaxDynamicSharedMemorySize, SMEM_BYTES);

    dim3 grid(HH, SSEQ / BM, BB);       // h fastest: concurrent CTAs share mask + K/V in L2
    attn_mma<<<grid, NTH, SMEM_BYTES>>>(q, k, v, mask, out, attn);

    size_t total4 = (size_t)BB * HH * SSEQ * SSEQ / 4;
    unsigned blocks = (unsigned)((total4 + 255) / 256);
    attn_norm<<<blocks, 256>>>(attn);
}